// round 5
// baseline (speedup 1.0000x reference)
#include <cuda_runtime.h>

// ---------------------------------------------------------------------------
// QCycleConv2d: out[b] = W rho[b] W^H, W = kron(w, ux (x) uy)
//   ux, uy: 16x16 circulant unitaries from phi[0:16], phi[16:32]
//   w = uc[:, 4:8] where uc = 8x8 Clements-mesh interferometer from phi[32:88]
// Kronecker structure -> 16-wide axis contractions instead of 2048-wide GEMMs.
// ---------------------------------------------------------------------------

__device__ float2 g_ux[256];   // ux[j*16+k]
__device__ float2 g_uy[256];   // uy[j*16+k]
__device__ float2 g_w[32];     // w[c*4+c1] = uc[c][4+c1]
__device__ float2 g_M1[(size_t)8 * 1024 * 1024];  // 67 MB scratch: (I4 (x) u) rho

static __device__ __forceinline__ float2 cmulf2(float2 a, float2 b) {
    return make_float2(a.x * b.x - a.y * b.y, a.x * b.y + a.y * b.x);
}
// c += a*b
static __device__ __forceinline__ void cfma_(float2& c, float2 a, float2 b) {
    c.x = fmaf(a.x, b.x, c.x); c.x = fmaf(-a.y, b.y, c.x);
    c.y = fmaf(a.x, b.y, c.y); c.y = fmaf( a.y, b.x, c.y);
}
// c += conj(a)*b
static __device__ __forceinline__ void cfma_cjA_(float2& c, float2 a, float2 b) {
    c.x = fmaf(a.x, b.x, c.x); c.x = fmaf( a.y, b.y, c.x);
    c.y = fmaf(a.x, b.y, c.y); c.y = fmaf(-a.y, b.x, c.y);
}
// c += a*conj(b)
static __device__ __forceinline__ void cfma_cjB_(float2& c, float2 a, float2 b) {
    c.x = fmaf(a.x, b.x, c.x); c.x = fmaf( a.y, b.y, c.x);
    c.y = fmaf(a.y, b.x, c.y); c.y = fmaf(-a.x, b.y, c.y);
}

// ---------------------------------------------------------------------------
// Precompute ux, uy, w from phi (88 floats). Tiny: 1 CTA.
// ---------------------------------------------------------------------------
__global__ void precompute_kernel(const float* __restrict__ phi) {
    __shared__ float2 cx[16], cy[16];
    int t = threadIdx.x;
    if (t < 32) {
        int d = t & 15;
        const float* p = phi + ((t < 16) ? 0 : 16);
        float sr = 0.f, si = 0.f;
        for (int m = 0; m < 16; m++) {
            float ang = p[m] + 6.283185307179586f * (float)((m * d) & 15) * 0.0625f;
            float s, c;
            sincosf(ang, &s, &c);
            sr += c; si += s;
        }
        float2 v = make_float2(sr * 0.0625f, si * 0.0625f);
        if (t < 16) cx[d] = v; else cy[d] = v;
    }
    __syncthreads();
    {
        int j = t >> 4, k = t & 15;
        int d = (j - k) & 15;
        g_ux[t] = cx[d];
        g_uy[t] = cy[d];
    }
    if (t == 0) {
        // 8-mode interferometer, replicated exactly (sequential MZI mesh).
        float2 U[8][8];
        for (int i = 0; i < 8; i++)
            for (int j = 0; j < 8; j++)
                U[i][j] = make_float2(i == j ? 1.f : 0.f, 0.f);
        const float* pc = phi + 32;
        int idx = 0;
        for (int layer = 0; layer < 8; layer++) {
            for (int m0 = (layer & 1); m0 < 7; m0 += 2) {
                float p1 = pc[idx], p2 = pc[idx + 1]; idx += 2;
                float s1, c1v, s2, c2v;
                sincosf(p1, &s1, &c1v);
                sincosf(p2, &s2, &c2v);
                // M = 0.5*[[e1*(e2+1), e2-1],[e1*(e2-1), e2+1]], e = exp(i phi)
                float2 e1  = make_float2(c1v, s1);
                float2 e2p = make_float2(c2v + 1.f, s2);
                float2 e2m = make_float2(c2v - 1.f, s2);
                float2 M00 = cmulf2(e1, e2p); M00.x *= 0.5f; M00.y *= 0.5f;
                float2 M01 = make_float2(0.5f * e2m.x, 0.5f * e2m.y);
                float2 M10 = cmulf2(e1, e2m); M10.x *= 0.5f; M10.y *= 0.5f;
                float2 M11 = make_float2(0.5f * e2p.x, 0.5f * e2p.y);
                for (int j = 0; j < 8; j++) {
                    float2 a = U[m0][j], bb = U[m0 + 1][j];
                    float2 r0 = cmulf2(M00, a); cfma_(r0, M01, bb);
                    float2 r1 = cmulf2(M10, a); cfma_(r1, M11, bb);
                    U[m0][j] = r0; U[m0 + 1][j] = r1;
                }
            }
        }
        for (int c = 0; c < 8; c++)
            for (int c1i = 0; c1i < 4; c1i++)
                g_w[c * 4 + c1i] = U[c][4 + c1i];
    }
}

// ---------------------------------------------------------------------------
// Pass A: M1[(c1,s), col] = sum_t u[s,t] * rho[(c1,t), col], u = ux (x) uy.
// CTA: (b, c1, 16-col chunk). Grid: 8*4*64 = 2048 CTAs.
// ---------------------------------------------------------------------------
__global__ void __launch_bounds__(256, 4) passA_kernel(const float* __restrict__ rr,
                                                       const float* __restrict__ ri) {
    __shared__ float2 sA[256 * 17];
    __shared__ float2 sux[256];
    __shared__ float2 suy[256];
    int t = threadIdx.x;
    sux[t] = g_ux[t];
    suy[t] = g_uy[t];
    int chunk = blockIdx.x & 63;
    int c1    = (blockIdx.x >> 6) & 3;
    int b     = blockIdx.x >> 8;
    size_t gbase = ((size_t)b << 20) + (size_t)(c1 << 8) * 1024 + (size_t)(chunk << 4);

#pragma unroll
    for (int i = 0; i < 16; i++) {
        int idx = t + (i << 8);
        int r = idx >> 4, cc = idx & 15;
        size_t g = gbase + (size_t)r * 1024 + cc;
        sA[r * 17 + cc] = make_float2(rr[g], ri[g]);
    }
    __syncthreads();

    // stage 1: contract inner (y) axis with uy[y][y1]
    {
        int x1 = t >> 4, cc = t & 15;
        float2 v[16];
#pragma unroll
        for (int y1 = 0; y1 < 16; y1++) v[y1] = sA[(x1 * 16 + y1) * 17 + cc];
        for (int y = 0; y < 16; y++) {
            float2 acc = make_float2(0.f, 0.f);
#pragma unroll
            for (int y1 = 0; y1 < 16; y1++) cfma_(acc, suy[y * 16 + y1], v[y1]);
            sA[(x1 * 16 + y) * 17 + cc] = acc;
        }
    }
    __syncthreads();

    // stage 2: contract outer (x) axis with ux[x][x1]
    {
        int y = t >> 4, cc = t & 15;
        float2 v[16];
#pragma unroll
        for (int x1 = 0; x1 < 16; x1++) v[x1] = sA[(x1 * 16 + y) * 17 + cc];
        for (int x = 0; x < 16; x++) {
            float2 acc = make_float2(0.f, 0.f);
#pragma unroll
            for (int x1 = 0; x1 < 16; x1++) cfma_(acc, sux[x * 16 + x1], v[x1]);
            sA[(x * 16 + y) * 17 + cc] = acc;
        }
    }
    __syncthreads();

#pragma unroll
    for (int i = 0; i < 16; i++) {
        int idx = t + (i << 8);
        int r = idx >> 4, cc = idx & 15;
        g_M1[gbase + (size_t)r * 1024 + cc] = sA[r * 17 + cc];
    }
}

// ---------------------------------------------------------------------------
// Pass B: right-apply u^H then the 8x4 channel sandwich; adaptive output:
//   interleaved==1 : O viewed as float2 (re,im) pairs, 2*out_floats capacity
//   interleaved==0 : O is float32 REAL PART only
// All stores bounds-guarded by cap_floats (element count of float32 slots).
// Grid: 8*256 = 2048 CTAs.
// ---------------------------------------------------------------------------
#define BST 1092
__global__ void __launch_bounds__(256, 3) passB_kernel(float* __restrict__ O,
                                                       long long cap_floats,
                                                       int interleaved) {
    __shared__ float2 sM[4 * BST];
    __shared__ float2 sux[256];
    __shared__ float2 suy[256];
    __shared__ float2 sw[32];
    int t = threadIdx.x;
    sux[t] = g_ux[t];
    suy[t] = g_uy[t];
    if (t < 32) sw[t] = g_w[t];
    int q = blockIdx.x & 255;
    int b = blockIdx.x >> 8;
    size_t mbase = ((size_t)b << 20) + (size_t)q * 1024;

#pragma unroll
    for (int i = 0; i < 16; i++) {
        int idx = t + (i << 8);           // 4096 = 4 rows x 1024 cols
        int row = idx >> 10, col = idx & 1023;
        sM[row * BST + col + (col >> 4)] =
            g_M1[mbase + (size_t)(row << 8) * 1024 + col];
    }
    __syncthreads();

    // stage 1: contract y1' with conj(uy[y'][y1'])
    {
        int x1 = t & 15, c2 = (t >> 4) & 3, row = t >> 6;
        int base = row * BST + c2 * 272 + x1 * 17;
        float2 v[16];
#pragma unroll
        for (int y1 = 0; y1 < 16; y1++) v[y1] = sM[base + y1];
        for (int y = 0; y < 16; y++) {
            float2 acc = make_float2(0.f, 0.f);
#pragma unroll
            for (int y1 = 0; y1 < 16; y1++) cfma_cjA_(acc, suy[y * 16 + y1], v[y1]);
            sM[base + y] = acc;
        }
    }
    __syncthreads();

    // stage 2: contract x1' with conj(ux[x'][x1'])
    {
        int yp = t & 15, c2 = (t >> 4) & 3, row = t >> 6;
        int base = row * BST + c2 * 272 + yp;
        float2 v[16];
#pragma unroll
        for (int x1 = 0; x1 < 16; x1++) v[x1] = sM[base + x1 * 17];
        for (int x = 0; x < 16; x++) {
            float2 acc = make_float2(0.f, 0.f);
#pragma unroll
            for (int x1 = 0; x1 < 16; x1++) cfma_cjA_(acc, sux[x * 16 + x1], v[x1]);
            sM[base + x * 17] = acc;
        }
    }
    __syncthreads();

    // stage 3: channel sandwich + guarded writes of all 64 (c,c') blocks
    {
        int sp = t;
        int spsw = sp + (sp >> 4);
        float2 m[4][4];
#pragma unroll
        for (int c1i = 0; c1i < 4; c1i++)
#pragma unroll
            for (int c2 = 0; c2 < 4; c2++)
                m[c1i][c2] = sM[c1i * BST + c2 * 272 + spsw];
        long long ob = ((long long)b << 22) + (long long)q * 2048 + sp;
        float2* O2 = (float2*)O;
        for (int c = 0; c < 8; c++) {
            float2 tc[4];
#pragma unroll
            for (int c2 = 0; c2 < 4; c2++) {
                float2 acc = make_float2(0.f, 0.f);
#pragma unroll
                for (int c1i = 0; c1i < 4; c1i++) cfma_(acc, sw[c * 4 + c1i], m[c1i][c2]);
                tc[c2] = acc;
            }
            long long obc = ob + (long long)c * (256 * 2048);
#pragma unroll
            for (int cp = 0; cp < 8; cp++) {
                float2 acc = make_float2(0.f, 0.f);
#pragma unroll
                for (int c2 = 0; c2 < 4; c2++) cfma_cjB_(acc, tc[c2], sw[cp * 4 + c2]);
                long long idx = obc + cp * 256;
                if (interleaved) {
                    if (2 * idx + 1 < cap_floats) O2[idx] = acc;
                } else {
                    if (idx < cap_floats) O[idx] = acc.x;   // real part only
                }
            }
        }
    }
}

extern "C" void kernel_launch(void* const* d_in, const int* in_sizes, int n_in,
                              void* d_out, int out_size) {
    // phi = smallest input (robust to element-count vs byte sizes).
    int phi_idx = 0;
    for (int i = 1; i < n_in; i++)
        if (in_sizes[i] < in_sizes[phi_idx]) phi_idx = i;

    int big0 = -1, big1 = -1;
    for (int i = 0; i < n_in; i++) {
        if (i == phi_idx) continue;
        if (big0 < 0) big0 = i; else big1 = i;
    }

    const float* phi = (const float*)d_in[phi_idx];
    const float *rr, *ri;
    if (phi_idx == 0) {          // alphabetical: phi, rho_imag, rho_real
        ri = (const float*)d_in[big0];
        rr = (const float*)d_in[big1];
    } else {                     // insertion: rho_real, rho_imag, phi
        rr = (const float*)d_in[big0];
        ri = (const float*)d_in[big1];
    }

    // Output layout: 8*2048*2048 = 33,554,432 complex values.
    // out_size >= 67,108,864 float32 slots -> interleaved (re,im) pairs.
    // otherwise (e.g. 33,554,432)          -> float32 real part only.
    const long long NC = 33554432LL;
    int interleaved = (out_size >= 2 * NC) ? 1 : 0;
    long long cap_floats = (long long)out_size;

    precompute_kernel<<<1, 256>>>(phi);
    passA_kernel<<<2048, 256>>>(rr, ri);
    passB_kernel<<<2048, 256>>>((float*)d_out, cap_floats, interleaved);
}

// round 6
// speedup vs baseline: 1.3437x; 1.3437x over previous
#include <cuda_runtime.h>
#include <cuda_fp16.h>

// ---------------------------------------------------------------------------
// QCycleConv2d: out[b] = W rho[b] W^H, W = kron(w, ux (x) uy)
//   ux, uy: 16x16 circulant unitaries from phi[0:16], phi[16:32]
//   w = uc[:, 4:8], uc = 8x8 Clements-mesh interferometer from phi[32:88]
// Kronecker structure -> 16-wide axis contractions instead of 2048-wide GEMMs.
// M1 intermediate is stored in fp16 (half traffic); fp16 noise ~1.4e-4 rel.
// ---------------------------------------------------------------------------

__device__ float2  g_ux[256];   // ux[j*16+k]
__device__ float2  g_uy[256];   // uy[j*16+k]
__device__ float2  g_w[32];     // w[c*4+c1] = uc[c][4+c1]
__device__ __half2 g_M1h[(size_t)8 * 1024 * 1024];  // 32 MB scratch (fp16 complex)

static __device__ __forceinline__ float2 cmulf2(float2 a, float2 b) {
    return make_float2(a.x * b.x - a.y * b.y, a.x * b.y + a.y * b.x);
}
// c += a*b
static __device__ __forceinline__ void cfma_(float2& c, float2 a, float2 b) {
    c.x = fmaf(a.x, b.x, c.x); c.x = fmaf(-a.y, b.y, c.x);
    c.y = fmaf(a.x, b.y, c.y); c.y = fmaf( a.y, b.x, c.y);
}
// c += conj(a)*b
static __device__ __forceinline__ void cfma_cjA_(float2& c, float2 a, float2 b) {
    c.x = fmaf(a.x, b.x, c.x); c.x = fmaf( a.y, b.y, c.x);
    c.y = fmaf(a.x, b.y, c.y); c.y = fmaf(-a.y, b.x, c.y);
}
// c += a*conj(b)
static __device__ __forceinline__ void cfma_cjB_(float2& c, float2 a, float2 b) {
    c.x = fmaf(a.x, b.x, c.x); c.x = fmaf( a.y, b.y, c.x);
    c.y = fmaf(a.y, b.x, c.y); c.y = fmaf(-a.x, b.y, c.y);
}

// ---------------------------------------------------------------------------
// Precompute ux, uy, w. All sincosf data-parallel; mesh is 8 threads, each
// owning one COLUMN of U in registers (MZIs only mix rows -> no cross-thread
// communication at all).
// ---------------------------------------------------------------------------
__global__ void precompute_kernel(const float* __restrict__ phi) {
    __shared__ float2 se[32];    // exp(i phi_m), x then y
    __shared__ float2 sw16[16];  // exp(2 pi i k/16)
    __shared__ float2 sme[56];   // exp(i phi_c[k]) for the mesh
    __shared__ float2 cx[16], cy[16];
    int t = threadIdx.x;

    if (t < 32) {
        float s, c; sincosf(phi[t], &s, &c);
        se[t] = make_float2(c, s);
    } else if (t < 48) {
        int k = t - 32;
        float s, c; sincosf(6.283185307179586f * (float)k * 0.0625f, &s, &c);
        sw16[k] = make_float2(c, s);
    } else if (t < 104) {
        int k = t - 48;
        float s, c; sincosf(phi[32 + k], &s, &c);
        sme[k] = make_float2(c, s);
    }
    __syncthreads();

    if (t < 32) {
        int grp = t >> 4, d = t & 15;
        float2 acc = make_float2(0.f, 0.f);
#pragma unroll
        for (int m = 0; m < 16; m++)
            cfma_(acc, se[grp * 16 + m], sw16[(m * d) & 15]);
        acc.x *= 0.0625f; acc.y *= 0.0625f;
        if (grp == 0) cx[d] = acc; else cy[d] = acc;
    }
    __syncthreads();

    {
        int j = t >> 4, k = t & 15;
        int d = (j - k) & 15;
        g_ux[t] = cx[d];
        g_uy[t] = cy[d];
    }

    if (t < 8) {
        // column j of uc, in registers
        float2 col[8];
#pragma unroll
        for (int i = 0; i < 8; i++) col[i] = make_float2(i == t ? 1.f : 0.f, 0.f);
        int idx = 0;
        for (int layer = 0; layer < 8; layer++) {
            for (int m0 = (layer & 1); m0 < 7; m0 += 2) {
                float2 e1 = sme[idx], e2 = sme[idx + 1]; idx += 2;
                float2 e2p = make_float2(e2.x + 1.f, e2.y);
                float2 e2m = make_float2(e2.x - 1.f, e2.y);
                float2 M00 = cmulf2(e1, e2p); M00.x *= 0.5f; M00.y *= 0.5f;
                float2 M01 = make_float2(0.5f * e2m.x, 0.5f * e2m.y);
                float2 M10 = cmulf2(e1, e2m); M10.x *= 0.5f; M10.y *= 0.5f;
                float2 M11 = make_float2(0.5f * e2p.x, 0.5f * e2p.y);
                float2 a = col[m0], bb = col[m0 + 1];
                float2 r0 = cmulf2(M00, a); cfma_(r0, M01, bb);
                float2 r1 = cmulf2(M10, a); cfma_(r1, M11, bb);
                col[m0] = r0; col[m0 + 1] = r1;
            }
        }
        if (t >= 4) {
            int c1 = t - 4;
#pragma unroll
            for (int c = 0; c < 8; c++) g_w[c * 4 + c1] = col[c];
        }
    }
}

// ---------------------------------------------------------------------------
// Pass A: M1[(c1,s), col] = sum_t u[s,t] * rho[(c1,t), col], u = ux (x) uy.
// CTA: (b, c1, 16-col chunk). Grid 2048. float4 gmem loads, fp16 M1 stores.
// ---------------------------------------------------------------------------
__global__ void __launch_bounds__(256, 4) passA_kernel(const float* __restrict__ rr,
                                                       const float* __restrict__ ri) {
    __shared__ float2 sA[256 * 17];
    __shared__ float2 sux[256];
    __shared__ float2 suy[256];
    int t = threadIdx.x;
    sux[t] = g_ux[t];
    suy[t] = g_uy[t];
    int chunk = blockIdx.x & 63;
    int c1    = (blockIdx.x >> 6) & 3;
    int b     = blockIdx.x >> 8;
    size_t gbase = ((size_t)b << 20) + ((size_t)c1 << 18) + (size_t)(chunk << 4);

    // load 256 rows x 16 cols, 16B vectorized (4 cols per lane)
    const float4* rr4 = (const float4*)rr;
    const float4* ri4 = (const float4*)ri;
    size_t g4base = gbase >> 2;
#pragma unroll
    for (int i = 0; i < 4; i++) {
        int idx = t + (i << 8);          // [0,1024)
        int r = idx >> 2, q4 = idx & 3;
        size_t g4 = g4base + (size_t)r * 256 + q4;
        float4 a = rr4[g4];
        float4 bb = ri4[g4];
        float2* dst = &sA[r * 17 + q4 * 4];
        dst[0] = make_float2(a.x, bb.x);
        dst[1] = make_float2(a.y, bb.y);
        dst[2] = make_float2(a.z, bb.z);
        dst[3] = make_float2(a.w, bb.w);
    }
    __syncthreads();

    // stage 1: contract inner (y) axis with uy[y][y1]
    {
        int x1 = t >> 4, cc = t & 15;
        float2 v[16];
#pragma unroll
        for (int y1 = 0; y1 < 16; y1++) v[y1] = sA[(x1 * 16 + y1) * 17 + cc];
        for (int y = 0; y < 16; y++) {
            float2 acc = make_float2(0.f, 0.f);
#pragma unroll
            for (int y1 = 0; y1 < 16; y1++) cfma_(acc, suy[y * 16 + y1], v[y1]);
            sA[(x1 * 16 + y) * 17 + cc] = acc;
        }
    }
    __syncthreads();

    // stage 2: contract outer (x) axis with ux[x][x1]
    {
        int y = t >> 4, cc = t & 15;
        float2 v[16];
#pragma unroll
        for (int x1 = 0; x1 < 16; x1++) v[x1] = sA[(x1 * 16 + y) * 17 + cc];
        for (int x = 0; x < 16; x++) {
            float2 acc = make_float2(0.f, 0.f);
#pragma unroll
            for (int x1 = 0; x1 < 16; x1++) cfma_(acc, sux[x * 16 + x1], v[x1]);
            sA[(x * 16 + y) * 17 + cc] = acc;
        }
    }
    __syncthreads();

    // store fp16, 8B vectorized (2 complex per lane)
#pragma unroll
    for (int i = 0; i < 8; i++) {
        int idx = t + (i << 8);          // [0,2048)
        int r = idx >> 3, k = idx & 7;
        int cc = k * 2;
        __half2 h0 = __float22half2_rn(sA[r * 17 + cc]);
        __half2 h1 = __float22half2_rn(sA[r * 17 + cc + 1]);
        uint2 pk;
        pk.x = *(unsigned int*)&h0;
        pk.y = *(unsigned int*)&h1;
        *(uint2*)(g_M1h + gbase + (size_t)r * 1024 + cc) = pk;
    }
}

// ---------------------------------------------------------------------------
// Pass B: right-apply u^H (two conjugate 16-wide contractions), then the
// 8x4 channel sandwich, writing all 64 (c,c') blocks.
// CTA: (b, q=s in [0,256)). Grid 2048. uint4 fp16 loads (4 complex/lane).
// smem cols swizzled: col -> col + (col>>4).
// ---------------------------------------------------------------------------
#define BST 1092
__global__ void __launch_bounds__(256, 3) passB_kernel(float2* __restrict__ O,
                                                       int full) {
    __shared__ float2 sM[4 * BST];
    __shared__ float2 sux[256];
    __shared__ float2 suy[256];
    __shared__ float2 sw[32];
    int t = threadIdx.x;
    sux[t] = g_ux[t];
    suy[t] = g_uy[t];
    if (t < 32) sw[t] = g_w[t];
    int q = blockIdx.x & 255;
    int b = blockIdx.x >> 8;
    size_t mbase = ((size_t)b << 20) + (size_t)q * 1024;

#pragma unroll
    for (int i = 0; i < 4; i++) {
        int idx = t + (i << 8);          // [0,1024) uint4s
        int row = idx >> 8, c4 = idx & 255;
        int col = c4 * 4;
        uint4 pk = *(const uint4*)(g_M1h + mbase + ((size_t)row << 18) + col);
        int sb = row * BST + col + (col >> 4);
        sM[sb + 0] = __half22float2(*(__half2*)&pk.x);
        sM[sb + 1] = __half22float2(*(__half2*)&pk.y);
        sM[sb + 2] = __half22float2(*(__half2*)&pk.z);
        sM[sb + 3] = __half22float2(*(__half2*)&pk.w);
    }
    __syncthreads();

    // stage 1: contract y1' with conj(uy[y'][y1'])
    {
        int x1 = t & 15, c2 = (t >> 4) & 3, row = t >> 6;
        int base = row * BST + c2 * 272 + x1 * 17;
        float2 v[16];
#pragma unroll
        for (int y1 = 0; y1 < 16; y1++) v[y1] = sM[base + y1];
        for (int y = 0; y < 16; y++) {
            float2 acc = make_float2(0.f, 0.f);
#pragma unroll
            for (int y1 = 0; y1 < 16; y1++) cfma_cjA_(acc, suy[y * 16 + y1], v[y1]);
            sM[base + y] = acc;
        }
    }
    __syncthreads();

    // stage 2: contract x1' with conj(ux[x'][x1'])
    {
        int yp = t & 15, c2 = (t >> 4) & 3, row = t >> 6;
        int base = row * BST + c2 * 272 + yp;
        float2 v[16];
#pragma unroll
        for (int x1 = 0; x1 < 16; x1++) v[x1] = sM[base + x1 * 17];
        for (int x = 0; x < 16; x++) {
            float2 acc = make_float2(0.f, 0.f);
#pragma unroll
            for (int x1 = 0; x1 < 16; x1++) cfma_cjA_(acc, sux[x * 16 + x1], v[x1]);
            sM[base + x * 17] = acc;
        }
    }
    __syncthreads();

    // stage 3: channel sandwich + writes of all 64 (c,c') blocks
    {
        int sp = t;
        int spsw = sp + (sp >> 4);
        float2 m[4][4];
#pragma unroll
        for (int c1i = 0; c1i < 4; c1i++)
#pragma unroll
            for (int c2 = 0; c2 < 4; c2++)
                m[c1i][c2] = sM[c1i * BST + c2 * 272 + spsw];
        size_t ob = ((size_t)b << 22) + (size_t)q * 2048 + sp;
        if (full) {
            for (int c = 0; c < 8; c++) {
                float2 tc[4];
#pragma unroll
                for (int c2 = 0; c2 < 4; c2++) {
                    float2 acc = make_float2(0.f, 0.f);
#pragma unroll
                    for (int c1i = 0; c1i < 4; c1i++) cfma_(acc, sw[c * 4 + c1i], m[c1i][c2]);
                    tc[c2] = acc;
                }
                size_t obc = ob + (size_t)c * (256 * 2048);
#pragma unroll
                for (int cp = 0; cp < 8; cp++) {
                    float2 acc = make_float2(0.f, 0.f);
#pragma unroll
                    for (int c2 = 0; c2 < 4; c2++) cfma_cjB_(acc, tc[c2], sw[cp * 4 + c2]);
                    O[obc + cp * 256] = acc;
                }
            }
        } else {
            // fallback: real-part-only float32 output
            float* Or = (float*)O;
            for (int c = 0; c < 8; c++) {
                float2 tc[4];
#pragma unroll
                for (int c2 = 0; c2 < 4; c2++) {
                    float2 acc = make_float2(0.f, 0.f);
#pragma unroll
                    for (int c1i = 0; c1i < 4; c1i++) cfma_(acc, sw[c * 4 + c1i], m[c1i][c2]);
                    tc[c2] = acc;
                }
                size_t obc = ob + (size_t)c * (256 * 2048);
#pragma unroll
                for (int cp = 0; cp < 8; cp++) {
                    float2 acc = make_float2(0.f, 0.f);
#pragma unroll
                    for (int c2 = 0; c2 < 4; c2++) cfma_cjB_(acc, tc[c2], sw[cp * 4 + c2]);
                    Or[obc + cp * 256] = acc.x;
                }
            }
        }
    }
}

extern "C" void kernel_launch(void* const* d_in, const int* in_sizes, int n_in,
                              void* d_out, int out_size) {
    // phi = smallest input (robust to element-count vs byte sizes).
    int phi_idx = 0;
    for (int i = 1; i < n_in; i++)
        if (in_sizes[i] < in_sizes[phi_idx]) phi_idx = i;

    int big0 = -1, big1 = -1;
    for (int i = 0; i < n_in; i++) {
        if (i == phi_idx) continue;
        if (big0 < 0) big0 = i; else big1 = i;
    }

    const float* phi = (const float*)d_in[phi_idx];
    const float *rr, *ri;
    if (phi_idx == 0) {          // alphabetical: phi, rho_imag, rho_real
        ri = (const float*)d_in[big0];
        rr = (const float*)d_in[big1];
    } else {                     // insertion: rho_real, rho_imag, phi
        rr = (const float*)d_in[big0];
        ri = (const float*)d_in[big1];
    }

    // out_size >= 2*33,554,432 float slots -> interleaved complex (verified).
    const long long NC = 33554432LL;
    int full = (out_size >= 2 * NC) ? 1 : 0;

    precompute_kernel<<<1, 256>>>(phi);
    passA_kernel<<<2048, 256>>>(rr, ri);
    passB_kernel<<<2048, 256>>>((float2*)d_out, full);
}